// round 12
// baseline (speedup 1.0000x reference)
#include <cuda_runtime.h>

// Detail_loss: loss = (mean|conv(dx,kh)| + mean|conv(dx,kv)|)/2, dx=infer-ref,
// fixed [-0.5,0,0.5] kernels broadcast over 3x3 channel pairs.
// Reduces to S = sum_c(infer-ref); accumulate |S[h,w+1]-S[h,w-1]| + |S[h+1,w]-S[h-1,w]|
// (zero pad), scaled by 1/(4 * N * 258 * 256).
//
// Smem-free streaming: each warp owns an 8-row x 128-col strip (64 strips/img,
// 784 blocks -> ~42 warps/SM). Rolling 3-row float4 register window for vertical
// grads; warp shuffles + scalar halo loads for horizontal. Fully unrolled row
// loop for front-batched LDG.128. Single kernel, atomic finalize.

#define H 256
#define W 256
#define C 3
#define RSTRIP 8
#define IMG (C * H * W)

__device__ double       g_acc   = 0.0;
__device__ unsigned int g_count = 0;

__device__ __forceinline__ float4 loadS4(const float* __restrict__ pi,
                                         const float* __restrict__ pr, int r) {
    const size_t ro = (size_t)r * W;
    float4 v = make_float4(0.f, 0.f, 0.f, 0.f);
    #pragma unroll
    for (int ch = 0; ch < C; ch++) {
        const size_t o = ro + (size_t)ch * (H * W);
        const float4 a = __ldg((const float4*)(pi + o));
        const float4 b = __ldg((const float4*)(pr + o));
        v.x += a.x - b.x; v.y += a.y - b.y;
        v.z += a.z - b.z; v.w += a.w - b.w;
    }
    return v;
}

__device__ __forceinline__ float loadS1(const float* __restrict__ pi,
                                        const float* __restrict__ pr, int r) {
    const size_t ro = (size_t)r * W;
    float v = 0.f;
    #pragma unroll
    for (int ch = 0; ch < C; ch++) {
        const size_t o = ro + (size_t)ch * (H * W);
        v += __ldg(pi + o) - __ldg(pr + o);
    }
    return v;
}

__global__ __launch_bounds__(256)
void dl_fused(const float* __restrict__ infer, const float* __restrict__ ref,
              float* __restrict__ out, int n_img)
{
    const int tid  = threadIdx.x;
    const int lane = tid & 31;
    const int wid  = tid >> 5;
    const int gw   = blockIdx.x * 8 + wid;   // global warp id = strip id
    const int n    = gw >> 6;                // image (64 strips per image)
    const int rem  = gw & 63;
    const int seg  = rem & 1;                // column segment 0/1
    const int rs   = rem >> 1;               // row strip 0..31
    const int r0   = rs * RSTRIP;
    const int c0   = seg * 128;
    const int col  = c0 + lane * 4;

    const float* pi = infer + (size_t)n * IMG + col;
    const float* pr = ref   + (size_t)n * IMG + col;

    // Halo column: lane 0 needs S[.,c0-1]; lane 31 needs S[.,c0+128].
    const bool wantHalo = (lane == 0) ? (c0 > 0)
                        : ((lane == 31) && (c0 + 128 < W));
    const int hoff = ((lane == 0) ? -1 : 128) - lane * 4;  // relative to col
    const float* hi = pi + hoff;
    const float* hr = pr + hoff;

    float4 a  = (r0 > 0) ? loadS4(pi, pr, r0 - 1) : make_float4(0.f, 0.f, 0.f, 0.f);
    float4 b  = loadS4(pi, pr, r0);
    float  bh = wantHalo ? loadS1(hi, hr, r0) : 0.f;

    float acc = 0.f;
    #pragma unroll
    for (int i = 0; i < RSTRIP; i++) {
        const int r = r0 + i;
        float4 c   = make_float4(0.f, 0.f, 0.f, 0.f);
        float  chv = 0.f;
        if (r + 1 < H) {                       // uniform per warp (last strip only)
            c = loadS4(pi, pr, r + 1);
            if (wantHalo) chv = loadS1(hi, hr, r + 1);
        }
        // horizontal gradients of row r (factor-2 grads; scaled at the end)
        float lf = __shfl_up_sync(0xffffffffu, b.w, 1);
        float rt = __shfl_down_sync(0xffffffffu, b.x, 1);
        if (lane == 0)  lf = bh;   // left halo (0 at image edge)
        if (lane == 31) rt = bh;   // right halo (0 at image edge)
        acc += fabsf(b.y - lf) + fabsf(b.z - b.x)
             + fabsf(b.w - b.y) + fabsf(rt  - b.z);
        // vertical gradients of row r
        acc += fabsf(c.x - a.x) + fabsf(c.y - a.y)
             + fabsf(c.z - a.z) + fabsf(c.w - a.w);
        a = b; b = c; bh = chv;
    }

    // ---- warp + block reduction ----
    #pragma unroll
    for (int o = 16; o; o >>= 1) acc += __shfl_down_sync(0xffffffffu, acc, o);
    __shared__ float wsum[8];
    if (lane == 0) wsum[wid] = acc;
    __syncthreads();
    if (tid == 0) {
        float t = 0.f;
        #pragma unroll
        for (int i = 0; i < 8; i++) t += wsum[i];
        atomicAdd(&g_acc, (double)t);
        __threadfence();
        const unsigned old = atomicAdd(&g_count, 1u);
        if (old == gridDim.x - 1u) {            // last block finalizes
            __threadfence();
            const double s = atomicAdd(&g_acc, 0.0);  // coherent read
            out[0] = (float)(s / (4.0 * (double)n_img * 258.0 * 256.0));
            g_acc   = 0.0;                      // reset for next graph replay
            g_count = 0u;
        }
    }
}

extern "C" void kernel_launch(void* const* d_in, const int* in_sizes, int n_in,
                              void* d_out, int out_size) {
    const float* infer = (const float*)d_in[0];
    const float* ref   = (const float*)d_in[1];
    const int n_img = in_sizes[0] / IMG;               // 2*7*7 = 98
    const int nblk  = n_img * 64 / 8;                  // 784
    dl_fused<<<nblk, 256>>>(infer, ref, (float*)d_out, n_img);
}

// round 16
// speedup vs baseline: 1.2651x; 1.2651x over previous
#include <cuda_runtime.h>

// Detail_loss: loss = (mean|conv(dx,kh)| + mean|conv(dx,kv)|)/2, dx=infer-ref,
// fixed [-0.5,0,0.5] kernels broadcast over 3x3 channel pairs.
// Reduces to S = sum_c(infer-ref); accumulate |S[h,w+1]-S[h,w-1]| + |S[h+1,w]-S[h-1,w]|
// (zero pad), scaled by 1/(4 * N * 258 * 256).
//
// Traffic-minimal design: warp owns 8 FULL-WIDTH rows (lane = 8 columns, 2xfloat4).
// Horizontal grads: in-register + 2 shuffles/row (no halo loads; image edge = 0).
// Vertical grads: rolling 3-row register window; warp-boundary rows exchanged
// via smem within the block; only block-tile top/bottom rows re-read from DRAM
// (2 per 64 rows -> 3.1% halo). 392 blocks, single kernel, atomic finalize.

#define H 256
#define W 256
#define C 3
#define IMG (C * H * W)
#define RSTRIP 8                 // rows per warp
#define TROWS (8 * RSTRIP)       // rows per block tile (64)

__device__ double       g_acc   = 0.0;
__device__ unsigned int g_count = 0;

// channel-summed diff for 8 columns of row r (base = image base + lane*8)
__device__ __forceinline__ void loadS8(const float* __restrict__ pi,
                                       const float* __restrict__ pr,
                                       int r, float4& u, float4& v) {
    const size_t ro = (size_t)r * W;
    u = make_float4(0.f, 0.f, 0.f, 0.f);
    v = make_float4(0.f, 0.f, 0.f, 0.f);
    #pragma unroll
    for (int ch = 0; ch < C; ch++) {
        const size_t o = ro + (size_t)ch * (H * W);
        const float4 a0 = __ldg((const float4*)(pi + o));
        const float4 a1 = __ldg((const float4*)(pi + o + 4));
        const float4 b0 = __ldg((const float4*)(pr + o));
        const float4 b1 = __ldg((const float4*)(pr + o + 4));
        u.x += a0.x - b0.x; u.y += a0.y - b0.y;
        u.z += a0.z - b0.z; u.w += a0.w - b0.w;
        v.x += a1.x - b1.x; v.y += a1.y - b1.y;
        v.z += a1.z - b1.z; v.w += a1.w - b1.w;
    }
}

__device__ __forceinline__ void vabs8(float& acc, const float4& p0, const float4& p1,
                                      const float4& q0, const float4& q1) {
    acc += fabsf(q0.x - p0.x) + fabsf(q0.y - p0.y)
         + fabsf(q0.z - p0.z) + fabsf(q0.w - p0.w)
         + fabsf(q1.x - p1.x) + fabsf(q1.y - p1.y)
         + fabsf(q1.z - p1.z) + fabsf(q1.w - p1.w);
}

__global__ __launch_bounds__(256)
void dl_fused(const float* __restrict__ infer, const float* __restrict__ ref,
              float* __restrict__ out, int n_img)
{
    __shared__ float srow[8][2][W];   // [warp][first/last S row][col]  (16 KB)
    __shared__ float wsum[8];

    const int tid  = threadIdx.x;
    const int lane = tid & 31;
    const int wid  = tid >> 5;
    const int n    = blockIdx.x >> 2;          // image
    const int tile = blockIdx.x & 3;           // 64-row tile within image
    const int tr0  = tile * TROWS;
    const int r0   = tr0 + wid * RSTRIP;       // this warp's first row
    const int col  = lane * 8;

    const float* pi = infer + (size_t)n * IMG + col;
    const float* pr = ref   + (size_t)n * IMG + col;

    // Block-tile vertical halo rows (only warps 0 and 7 need a global row).
    float4 h0 = make_float4(0.f, 0.f, 0.f, 0.f), h1 = h0;
    if (wid == 0 && tr0 > 0)         loadS8(pi, pr, tr0 - 1,   h0, h1);
    if (wid == 7 && tr0 + TROWS < H) loadS8(pi, pr, tr0 + TROWS, h0, h1);

    // Rolling window: a = S[r-1], b = S[r], c = S[r+1]
    float4 a0, a1, b0, b1;
    loadS8(pi, pr, r0, b0, b1);
    *(float4*)&srow[wid][0][col]     = b0;     // publish S[r0]
    *(float4*)&srow[wid][0][col + 4] = b1;

    float4 s1a, s1b, s6a, s6b;                 // S[r0+1], S[r0+6] kept for boundary terms
    float acc = 0.f;

    #pragma unroll
    for (int i = 0; i < RSTRIP; i++) {
        float4 c0 = make_float4(0.f, 0.f, 0.f, 0.f), c1 = c0;
        if (i < RSTRIP - 1) loadS8(pi, pr, r0 + i + 1, c0, c1);
        if (i == 0) { s1a = c0; s1b = c1; }
        if (i == 5) { s6a = c0; s6b = c1; }
        if (i == 6) {                           // publish S[r0+7]
            *(float4*)&srow[wid][1][col]     = c0;
            *(float4*)&srow[wid][1][col + 4] = c1;
        }
        // horizontal gradients of row r0+i (factor-2 grads; scaled at end)
        float lf = __shfl_up_sync(0xffffffffu, b1.w, 1);
        float rt = __shfl_down_sync(0xffffffffu, b0.x, 1);
        if (lane == 0)  lf = 0.f;               // image left edge
        if (lane == 31) rt = 0.f;               // image right edge
        acc += fabsf(b0.y - lf)   + fabsf(b0.z - b0.x)
             + fabsf(b0.w - b0.y) + fabsf(b1.x - b0.z)
             + fabsf(b1.y - b0.w) + fabsf(b1.z - b1.x)
             + fabsf(b1.w - b1.y) + fabsf(rt   - b1.z);
        // vertical gradient at row r0+i for interior rows (needs a and c)
        if (i >= 1 && i <= RSTRIP - 2) vabs8(acc, a0, a1, c0, c1);
        a0 = b0; a1 = b1; b0 = c0; b1 = c1;
    }

    __syncthreads();

    // Boundary vertical terms: row r0 uses S[r0-1]; row r0+7 uses S[r0+8].
    float4 up0, up1, dn0, dn1;
    if (wid == 0) { up0 = h0; up1 = h1; }
    else {
        up0 = *(const float4*)&srow[wid - 1][1][col];
        up1 = *(const float4*)&srow[wid - 1][1][col + 4];
    }
    if (wid == 7) { dn0 = h0; dn1 = h1; }
    else {
        dn0 = *(const float4*)&srow[wid + 1][0][col];
        dn1 = *(const float4*)&srow[wid + 1][0][col + 4];
    }
    vabs8(acc, up0, up1, s1a, s1b);   // |S[r0+1] - S[r0-1]|
    vabs8(acc, s6a, s6b, dn0, dn1);   // |S[r0+8] - S[r0+6]|

    // ---- warp + block reduction ----
    #pragma unroll
    for (int o = 16; o; o >>= 1) acc += __shfl_down_sync(0xffffffffu, acc, o);
    if (lane == 0) wsum[wid] = acc;
    __syncthreads();
    if (tid == 0) {
        float t = 0.f;
        #pragma unroll
        for (int i = 0; i < 8; i++) t += wsum[i];
        atomicAdd(&g_acc, (double)t);
        __threadfence();
        const unsigned old = atomicAdd(&g_count, 1u);
        if (old == gridDim.x - 1u) {            // last block finalizes
            __threadfence();
            const double s = atomicAdd(&g_acc, 0.0);  // coherent read
            out[0] = (float)(s / (4.0 * (double)n_img * 258.0 * 256.0));
            g_acc   = 0.0;                      // reset for next graph replay
            g_count = 0u;
        }
    }
}

extern "C" void kernel_launch(void* const* d_in, const int* in_sizes, int n_in,
                              void* d_out, int out_size) {
    const float* infer = (const float*)d_in[0];
    const float* ref   = (const float*)d_in[1];
    const int n_img = in_sizes[0] / IMG;               // 2*7*7 = 98
    dl_fused<<<n_img * 4, 256>>>(infer, ref, (float*)d_out, n_img);
}